// round 1
// baseline (speedup 1.0000x reference)
#include <cuda_runtime.h>
#include <cuda_bf16.h>
#include <cstdint>

#define NUM_USERS 50000
#define NUM_ITEMS 50000
#define N_NODES   100000
#define HIDDEN    128
#define N_EDGES   1600000

// ---------------------------------------------------------------------------
// Scratch (static device globals; no runtime allocation)
// ---------------------------------------------------------------------------
__device__ float g_x0[(size_t)N_NODES * HIDDEN];   // layer-0 input (concat)
__device__ float g_x1[(size_t)N_NODES * HIDDEN];   // layer-0 output
__device__ float g_agg[(size_t)N_NODES * HIDDEN];  // scatter accumulator
__device__ float g_deg[N_NODES];                   // deg, then inv_deg in place

// ---------------------------------------------------------------------------
// concat: g_x0 = [user_emb ; item_emb]   (float4 copies)
// ---------------------------------------------------------------------------
__global__ void concat_kernel(const float* __restrict__ ue,
                              const float* __restrict__ ie) {
    size_t i = (size_t)blockIdx.x * blockDim.x + threadIdx.x;
    const size_t half4 = (size_t)NUM_USERS * HIDDEN / 4;  // 1.6M float4
    if (i < half4) {
        ((float4*)g_x0)[i] = ((const float4*)ue)[i];
    } else if (i < 2 * half4) {
        ((float4*)g_x0)[i] = ((const float4*)ie)[i - half4];
    }
}

// ---------------------------------------------------------------------------
// zero agg (+ optionally deg)
// ---------------------------------------------------------------------------
__global__ void zero_agg_deg_kernel(int also_deg) {
    size_t i = (size_t)blockIdx.x * blockDim.x + threadIdx.x;
    const size_t n4 = (size_t)N_NODES * HIDDEN / 4;  // 3.2M float4
    if (i < n4) ((float4*)g_agg)[i] = make_float4(0.f, 0.f, 0.f, 0.f);
    if (also_deg && i < N_NODES) g_deg[i] = 0.f;
}

// ---------------------------------------------------------------------------
// degree count (atomic) then inv transform
// ---------------------------------------------------------------------------
__global__ void deg_kernel(const int* __restrict__ ei) {
    int e = blockIdx.x * blockDim.x + threadIdx.x;
    if (e < N_EDGES) {
        int dst = __ldg(ei + N_EDGES + e);
        atomicAdd(&g_deg[dst], 1.0f);
    }
}

__global__ void inv_kernel() {
    int i = blockIdx.x * blockDim.x + threadIdx.x;
    if (i < N_NODES) g_deg[i] = 1.0f / fmaxf(g_deg[i], 1.0f);
}

// ---------------------------------------------------------------------------
// scatter: agg[dst] += x[src]   one warp per edge, float4 lanes,
// vectorized L2 reduction (red.global.add.v4.f32, sm_90+)
// ---------------------------------------------------------------------------
__global__ void scatter_kernel(const float* __restrict__ x,
                               const int* __restrict__ ei) {
    int w = (int)(((size_t)blockIdx.x * blockDim.x + threadIdx.x) >> 5);
    int lane = threadIdx.x & 31;
    if (w >= N_EDGES) return;
    int src = __ldg(ei + w);
    int dst = __ldg(ei + N_EDGES + w);
    float4 v = *(const float4*)(x + (size_t)src * HIDDEN + lane * 4);
    float* p = g_agg + (size_t)dst * HIDDEN + lane * 4;
    asm volatile("red.global.add.v4.f32 [%0], {%1,%2,%3,%4};"
                 :: "l"(p), "f"(v.x), "f"(v.y), "f"(v.z), "f"(v.w)
                 : "memory");
}

// ---------------------------------------------------------------------------
// fused GEMM: out = relu( (inv_deg .* agg) @ Wl^T + b + xin @ Wr^T )
// M=100000, N=128, K=256 (k<128 -> agg/Wl ; k>=128 -> xin/Wr)
// block tile 64x128, thread tile 4x8, 256 threads
// ---------------------------------------------------------------------------
__global__ __launch_bounds__(256) void gemm_relu_kernel(
    const float* __restrict__ xin,
    const float* __restrict__ Wl,
    const float* __restrict__ Wr,
    const float* __restrict__ bias,
    float* __restrict__ out) {
    __shared__ float As[16][64];    // [k][m]
    __shared__ float Ws[16][128];   // [k][n]

    const int tid = threadIdx.x;
    const int tx  = tid & 15;        // 0..15  -> n block (8 cols each)
    const int ty  = tid >> 4;        // 0..15  -> m block (4 rows each)
    const int m0  = blockIdx.x * 64;

    const int lr = tid >> 2;         // 0..63  A-tile row
    const int lc = (tid & 3) << 2;   // 0,4,8,12 A-tile col group

    float acc[4][8];
#pragma unroll
    for (int i = 0; i < 4; i++)
#pragma unroll
        for (int j = 0; j < 8; j++) acc[i][j] = 0.f;

    const int arow = m0 + lr;
    const bool arow_ok = (arow < N_NODES);
    const float invd = arow_ok ? g_deg[arow] : 0.f;   // holds inv_deg here

    for (int kc = 0; kc < 16; ++kc) {
        const int kk = kc << 4;
        const bool firstHalf = (kk < HIDDEN);
        const int ko = firstHalf ? kk : kk - HIDDEN;
        const float* Asrc = firstHalf ? g_agg : xin;
        const float* Wsrc = firstHalf ? Wl : Wr;

        float4 av = make_float4(0.f, 0.f, 0.f, 0.f);
        if (arow_ok)
            av = *(const float4*)(Asrc + (size_t)arow * HIDDEN + ko + lc);
        if (firstHalf) { av.x *= invd; av.y *= invd; av.z *= invd; av.w *= invd; }
        As[lc + 0][lr] = av.x;
        As[lc + 1][lr] = av.y;
        As[lc + 2][lr] = av.z;
        As[lc + 3][lr] = av.w;

#pragma unroll
        for (int r = 0; r < 2; r++) {
            int idx = tid + (r << 8);       // 0..511
            int j   = idx >> 2;             // 0..127 weight row (n)
            int cg  = (idx & 3) << 2;       // col group in k
            float4 wv = *(const float4*)(Wsrc + j * HIDDEN + ko + cg);
            Ws[cg + 0][j] = wv.x;
            Ws[cg + 1][j] = wv.y;
            Ws[cg + 2][j] = wv.z;
            Ws[cg + 3][j] = wv.w;
        }
        __syncthreads();

#pragma unroll
        for (int k = 0; k < 16; k++) {
            float4 a  = *(const float4*)&As[k][ty << 2];
            float4 w0 = *(const float4*)&Ws[k][tx << 3];
            float4 w1 = *(const float4*)&Ws[k][(tx << 3) + 4];
            float ar[4] = {a.x, a.y, a.z, a.w};
            float wr[8] = {w0.x, w0.y, w0.z, w0.w, w1.x, w1.y, w1.z, w1.w};
#pragma unroll
            for (int i = 0; i < 4; i++)
#pragma unroll
                for (int j = 0; j < 8; j++)
                    acc[i][j] += ar[i] * wr[j];
        }
        __syncthreads();
    }

    // epilogue: bias + relu
    float4 b0 = *(const float4*)(bias + (tx << 3));
    float4 b1 = *(const float4*)(bias + (tx << 3) + 4);
    float bb[8] = {b0.x, b0.y, b0.z, b0.w, b1.x, b1.y, b1.z, b1.w};
#pragma unroll
    for (int i = 0; i < 4; i++) {
        int row = m0 + (ty << 2) + i;
        if (row < N_NODES) {
            float4 o0, o1;
            o0.x = fmaxf(acc[i][0] + bb[0], 0.f);
            o0.y = fmaxf(acc[i][1] + bb[1], 0.f);
            o0.z = fmaxf(acc[i][2] + bb[2], 0.f);
            o0.w = fmaxf(acc[i][3] + bb[3], 0.f);
            o1.x = fmaxf(acc[i][4] + bb[4], 0.f);
            o1.y = fmaxf(acc[i][5] + bb[5], 0.f);
            o1.z = fmaxf(acc[i][6] + bb[6], 0.f);
            o1.w = fmaxf(acc[i][7] + bb[7], 0.f);
            *(float4*)(out + (size_t)row * HIDDEN + (tx << 3)) = o0;
            *(float4*)(out + (size_t)row * HIDDEN + (tx << 3) + 4) = o1;
        }
    }
}

// ---------------------------------------------------------------------------
// launch
// ---------------------------------------------------------------------------
extern "C" void kernel_launch(void* const* d_in, const int* in_sizes, int n_in,
                              void* d_out, int out_size) {
    const float* ue = (const float*)d_in[0];
    const float* ie = (const float*)d_in[1];
    const float* Wl = (const float*)d_in[2];
    const float* bl = (const float*)d_in[3];
    const float* Wr = (const float*)d_in[4];
    const int*   ei = (const int*)d_in[5];
    float* out = (float*)d_out;

    float *px0, *px1;
    cudaGetSymbolAddress((void**)&px0, g_x0);
    cudaGetSymbolAddress((void**)&px1, g_x1);

    const int T = 256;
    const int concat_blocks = (int)(((size_t)2 * NUM_USERS * HIDDEN / 4 + T - 1) / T);
    const int zero_blocks   = (int)(((size_t)N_NODES * HIDDEN / 4 + T - 1) / T);
    const int deg_blocks    = (N_EDGES + T - 1) / T;
    const int inv_blocks    = (N_NODES + T - 1) / T;
    const int scat_blocks   = (int)(((size_t)N_EDGES * 32 + T - 1) / T);
    const int gemm_blocks   = (N_NODES + 63) / 64;

    // prologue: concat + degrees
    concat_kernel<<<concat_blocks, T>>>(ue, ie);
    zero_agg_deg_kernel<<<zero_blocks, T>>>(1);
    deg_kernel<<<deg_blocks, T>>>(ei);
    inv_kernel<<<inv_blocks, T>>>();

    // layer 0
    scatter_kernel<<<scat_blocks, T>>>(px0, ei);
    gemm_relu_kernel<<<gemm_blocks, 256>>>(px0, Wl, Wr, bl, px1);

    // layer 1
    zero_agg_deg_kernel<<<zero_blocks, T>>>(0);
    scatter_kernel<<<scat_blocks, T>>>(px1, ei);
    gemm_relu_kernel<<<gemm_blocks, 256>>>(px1, Wl + HIDDEN * HIDDEN,
                                           Wr + HIDDEN * HIDDEN,
                                           bl + HIDDEN, out);
}

// round 2
// speedup vs baseline: 1.4313x; 1.4313x over previous
#include <cuda_runtime.h>
#include <cuda_bf16.h>
#include <cstdint>

#define NUM_USERS 50000
#define NUM_ITEMS 50000
#define N_NODES   100000
#define HIDDEN    128
#define N_EDGES   1600000

#define SCAN_BLOCK 256
#define SCAN_NBLK  ((N_NODES + SCAN_BLOCK - 1) / SCAN_BLOCK)   // 391

// ---------------------------------------------------------------------------
// Scratch (static device globals; no runtime allocation)
// ---------------------------------------------------------------------------
__device__ float g_x1[(size_t)N_NODES * HIDDEN];   // layer-0 output
__device__ float g_agg[(size_t)N_NODES * HIDDEN];  // aggregated (already /deg)
__device__ int   g_cnt[N_NODES];                   // per-dst degree
__device__ int   g_incl[N_NODES];                  // block-local inclusive scan
__device__ int   g_rowptr[N_NODES + 1];
__device__ int   g_cursor[N_NODES];                // fill cursors
__device__ int   g_col[N_EDGES];                   // CSR column (src) indices
__device__ int   g_blocksum[SCAN_NBLK];

// ---------------------------------------------------------------------------
// CSR build: zero -> histogram -> 3-phase scan -> fill
// ---------------------------------------------------------------------------
__global__ void zero_cnt_kernel() {
    int i = blockIdx.x * blockDim.x + threadIdx.x;
    if (i < N_NODES) g_cnt[i] = 0;
}

__global__ void hist_kernel(const int* __restrict__ ei) {
    int e = blockIdx.x * blockDim.x + threadIdx.x;
    if (e < N_EDGES) atomicAdd(&g_cnt[__ldg(ei + N_EDGES + e)], 1);
}

// per-block inclusive scan of cnt; blocksum[b] = block total
__global__ void scanA_kernel() {
    __shared__ int s[SCAN_BLOCK];
    int t = threadIdx.x;
    int i = blockIdx.x * SCAN_BLOCK + t;
    int v = (i < N_NODES) ? g_cnt[i] : 0;
    s[t] = v;
    for (int off = 1; off < SCAN_BLOCK; off <<= 1) {
        __syncthreads();
        int u = (t >= off) ? s[t - off] : 0;
        __syncthreads();
        s[t] += u;
    }
    __syncthreads();
    if (i < N_NODES) g_incl[i] = s[t];
    if (t == SCAN_BLOCK - 1) g_blocksum[blockIdx.x] = s[t];
}

// single-block exclusive scan of blocksums (391 <= 512)
__global__ void scanB_kernel() {
    __shared__ int s[512];
    int t = threadIdx.x;
    int v = (t < SCAN_NBLK) ? g_blocksum[t] : 0;
    s[t] = v;
    for (int off = 1; off < 512; off <<= 1) {
        __syncthreads();
        int u = (t >= off) ? s[t - off] : 0;
        __syncthreads();
        s[t] += u;
    }
    __syncthreads();
    if (t < SCAN_NBLK) g_blocksum[t] = s[t] - v;   // exclusive
}

// rowptr[i] = blockoff + incl - cnt ; cursor = rowptr
__global__ void scanC_kernel() {
    int i = blockIdx.x * blockDim.x + threadIdx.x;
    if (i < N_NODES) {
        int excl = g_blocksum[i / SCAN_BLOCK] + g_incl[i] - g_cnt[i];
        g_rowptr[i] = excl;
        g_cursor[i] = excl;
    }
    if (i == 0) g_rowptr[N_NODES] = N_EDGES;
}

__global__ void fill_kernel(const int* __restrict__ ei) {
    int e = blockIdx.x * blockDim.x + threadIdx.x;
    if (e < N_EDGES) {
        int src = __ldg(ei + e);
        int dst = __ldg(ei + N_EDGES + e);
        int pos = atomicAdd(&g_cursor[dst], 1);
        g_col[pos] = src;
    }
}

// ---------------------------------------------------------------------------
// gather: agg[n] = (1/max(deg,1)) * sum_{e in CSR row n} x[col[e]]
// one warp per node, float4 accumulators (4 floats/lane * 32 lanes = 128)
// xu/xi: row r < NUM_USERS -> xu + r*H, else xi + (r-NUM_USERS)*H
// ---------------------------------------------------------------------------
__device__ __forceinline__ const float4* xrow(const float* xu, const float* xi,
                                              int r, int lane) {
    const float* base = (r < NUM_USERS) ? (xu + (size_t)r * HIDDEN)
                                        : (xi + (size_t)(r - NUM_USERS) * HIDDEN);
    return (const float4*)(base + lane * 4);
}

__global__ __launch_bounds__(256) void gather_kernel(
    const float* __restrict__ xu, const float* __restrict__ xi) {
    int node = blockIdx.x * (blockDim.x >> 5) + (threadIdx.x >> 5);
    int lane = threadIdx.x & 31;
    if (node >= N_NODES) return;
    int beg = g_rowptr[node];
    int end = g_rowptr[node + 1];
    float invd = 1.0f / fmaxf((float)(end - beg), 1.0f);

    float4 acc = make_float4(0.f, 0.f, 0.f, 0.f);
    int e = beg;
    for (; e + 4 <= end; e += 4) {
        int s0 = __ldg(&g_col[e]);
        int s1 = __ldg(&g_col[e + 1]);
        int s2 = __ldg(&g_col[e + 2]);
        int s3 = __ldg(&g_col[e + 3]);
        float4 v0 = *xrow(xu, xi, s0, lane);
        float4 v1 = *xrow(xu, xi, s1, lane);
        float4 v2 = *xrow(xu, xi, s2, lane);
        float4 v3 = *xrow(xu, xi, s3, lane);
        acc.x += v0.x + v1.x + v2.x + v3.x;
        acc.y += v0.y + v1.y + v2.y + v3.y;
        acc.z += v0.z + v1.z + v2.z + v3.z;
        acc.w += v0.w + v1.w + v2.w + v3.w;
    }
    for (; e < end; e++) {
        int s0 = __ldg(&g_col[e]);
        float4 v0 = *xrow(xu, xi, s0, lane);
        acc.x += v0.x; acc.y += v0.y; acc.z += v0.z; acc.w += v0.w;
    }
    acc.x *= invd; acc.y *= invd; acc.z *= invd; acc.w *= invd;
    *(float4*)(g_agg + (size_t)node * HIDDEN + lane * 4) = acc;
}

// ---------------------------------------------------------------------------
// fused GEMM: out = relu( agg @ Wl^T + b + x @ Wr^T )
// (agg already includes inv_deg). M=100000, N=128, K=256.
// block tile 64x128, thread tile 4x8, 256 threads
// ---------------------------------------------------------------------------
__global__ __launch_bounds__(256) void gemm_relu_kernel(
    const float* __restrict__ xu,
    const float* __restrict__ xi,
    const float* __restrict__ Wl,
    const float* __restrict__ Wr,
    const float* __restrict__ bias,
    float* __restrict__ out) {
    __shared__ float As[16][64];    // [k][m]
    __shared__ float Ws[16][128];   // [k][n]

    const int tid = threadIdx.x;
    const int tx  = tid & 15;        // n block (8 cols each)
    const int ty  = tid >> 4;        // m block (4 rows each)
    const int m0  = blockIdx.x * 64;

    const int lr = tid >> 2;         // 0..63  A-tile row
    const int lc = (tid & 3) << 2;   // 0,4,8,12 A-tile col group

    float acc[4][8];
#pragma unroll
    for (int i = 0; i < 4; i++)
#pragma unroll
        for (int j = 0; j < 8; j++) acc[i][j] = 0.f;

    const int arow = m0 + lr;
    const bool arow_ok = (arow < N_NODES);
    const float* aggrow = g_agg + (size_t)arow * HIDDEN;
    const float* xinrow = arow_ok
        ? ((arow < NUM_USERS) ? xu + (size_t)arow * HIDDEN
                              : xi + (size_t)(arow - NUM_USERS) * HIDDEN)
        : xu;

    for (int kc = 0; kc < 16; ++kc) {
        const int kk = kc << 4;
        const bool firstHalf = (kk < HIDDEN);
        const int ko = firstHalf ? kk : kk - HIDDEN;
        const float* Arow = firstHalf ? aggrow : xinrow;
        const float* Wsrc = firstHalf ? Wl : Wr;

        float4 av = make_float4(0.f, 0.f, 0.f, 0.f);
        if (arow_ok) av = *(const float4*)(Arow + ko + lc);
        As[lc + 0][lr] = av.x;
        As[lc + 1][lr] = av.y;
        As[lc + 2][lr] = av.z;
        As[lc + 3][lr] = av.w;

#pragma unroll
        for (int r = 0; r < 2; r++) {
            int idx = tid + (r << 8);       // 0..511
            int j   = idx >> 2;             // 0..127 weight row (n)
            int cg  = (idx & 3) << 2;       // col group in k
            float4 wv = *(const float4*)(Wsrc + j * HIDDEN + ko + cg);
            Ws[cg + 0][j] = wv.x;
            Ws[cg + 1][j] = wv.y;
            Ws[cg + 2][j] = wv.z;
            Ws[cg + 3][j] = wv.w;
        }
        __syncthreads();

#pragma unroll
        for (int k = 0; k < 16; k++) {
            float4 a  = *(const float4*)&As[k][ty << 2];
            float4 w0 = *(const float4*)&Ws[k][tx << 3];
            float4 w1 = *(const float4*)&Ws[k][(tx << 3) + 4];
            float ar[4] = {a.x, a.y, a.z, a.w};
            float wr[8] = {w0.x, w0.y, w0.z, w0.w, w1.x, w1.y, w1.z, w1.w};
#pragma unroll
            for (int i = 0; i < 4; i++)
#pragma unroll
                for (int j = 0; j < 8; j++)
                    acc[i][j] += ar[i] * wr[j];
        }
        __syncthreads();
    }

    // epilogue: bias + relu
    float4 b0 = *(const float4*)(bias + (tx << 3));
    float4 b1 = *(const float4*)(bias + (tx << 3) + 4);
    float bb[8] = {b0.x, b0.y, b0.z, b0.w, b1.x, b1.y, b1.z, b1.w};
#pragma unroll
    for (int i = 0; i < 4; i++) {
        int row = m0 + (ty << 2) + i;
        if (row < N_NODES) {
            float4 o0, o1;
            o0.x = fmaxf(acc[i][0] + bb[0], 0.f);
            o0.y = fmaxf(acc[i][1] + bb[1], 0.f);
            o0.z = fmaxf(acc[i][2] + bb[2], 0.f);
            o0.w = fmaxf(acc[i][3] + bb[3], 0.f);
            o1.x = fmaxf(acc[i][4] + bb[4], 0.f);
            o1.y = fmaxf(acc[i][5] + bb[5], 0.f);
            o1.z = fmaxf(acc[i][6] + bb[6], 0.f);
            o1.w = fmaxf(acc[i][7] + bb[7], 0.f);
            *(float4*)(out + (size_t)row * HIDDEN + (tx << 3)) = o0;
            *(float4*)(out + (size_t)row * HIDDEN + (tx << 3) + 4) = o1;
        }
    }
}

// ---------------------------------------------------------------------------
// launch
// ---------------------------------------------------------------------------
extern "C" void kernel_launch(void* const* d_in, const int* in_sizes, int n_in,
                              void* d_out, int out_size) {
    const float* ue = (const float*)d_in[0];
    const float* ie = (const float*)d_in[1];
    const float* Wl = (const float*)d_in[2];
    const float* bl = (const float*)d_in[3];
    const float* Wr = (const float*)d_in[4];
    const int*   ei = (const int*)d_in[5];
    float* out = (float*)d_out;

    float* px1;
    cudaGetSymbolAddress((void**)&px1, g_x1);

    const int T = 256;
    const int node_blocks = (N_NODES + T - 1) / T;        // 391
    const int edge_blocks = (N_EDGES + T - 1) / T;        // 6250
    const int gath_blocks = (N_NODES + 7) / 8;            // 8 warps/block
    const int gemm_blocks = (N_NODES + 63) / 64;          // 1563

    // CSR build (once; reused by both layers)
    zero_cnt_kernel<<<node_blocks, T>>>();
    hist_kernel<<<edge_blocks, T>>>(ei);
    scanA_kernel<<<SCAN_NBLK, SCAN_BLOCK>>>();
    scanB_kernel<<<1, 512>>>();
    scanC_kernel<<<node_blocks, T>>>();
    fill_kernel<<<edge_blocks, T>>>(ei);

    // layer 0 (x = [ue ; ie] virtually)
    gather_kernel<<<gath_blocks, T>>>(ue, ie);
    gemm_relu_kernel<<<gemm_blocks, 256>>>(ue, ie, Wl, Wr, bl, px1);

    // layer 1 (x = g_x1; split pointers line up contiguously)
    gather_kernel<<<gath_blocks, T>>>(px1, px1 + (size_t)NUM_USERS * HIDDEN);
    gemm_relu_kernel<<<gemm_blocks, 256>>>(px1, px1 + (size_t)NUM_USERS * HIDDEN,
                                           Wl + HIDDEN * HIDDEN,
                                           Wr + HIDDEN * HIDDEN,
                                           bl + HIDDEN, out);
}

// round 3
// speedup vs baseline: 2.0637x; 1.4418x over previous
#include <cuda_runtime.h>
#include <cuda_bf16.h>
#include <cstdint>

#define NUM_USERS 50000
#define NUM_ITEMS 50000
#define N_NODES   100000
#define HIDDEN    128
#define N_EDGES   1600000

#define SCAN_BLOCK 256
#define SCAN_NBLK  ((N_NODES + SCAN_BLOCK - 1) / SCAN_BLOCK)   // 391

// ---------------------------------------------------------------------------
// Scratch (static device globals; no runtime allocation)
// ---------------------------------------------------------------------------
__device__ float g_x1[(size_t)N_NODES * HIDDEN];   // layer-0 output
__device__ float g_agg[(size_t)N_NODES * HIDDEN];  // aggregated (already /deg)
__device__ int   g_cnt[N_NODES];
__device__ int   g_incl[N_NODES];
__device__ int   g_rowptr[N_NODES + 1];
__device__ int   g_cursor[N_NODES];
__device__ int   g_col[N_EDGES];
__device__ int   g_blocksum[SCAN_NBLK];

// ---------------------------------------------------------------------------
// CSR build: zero -> histogram -> 3-phase scan -> fill
// ---------------------------------------------------------------------------
__global__ void zero_cnt_kernel() {
    int i = blockIdx.x * blockDim.x + threadIdx.x;
    if (i < N_NODES) g_cnt[i] = 0;
}

__global__ void hist_kernel(const int* __restrict__ ei) {
    int e = blockIdx.x * blockDim.x + threadIdx.x;
    if (e < N_EDGES) atomicAdd(&g_cnt[__ldg(ei + N_EDGES + e)], 1);
}

__global__ void scanA_kernel() {
    __shared__ int s[SCAN_BLOCK];
    int t = threadIdx.x;
    int i = blockIdx.x * SCAN_BLOCK + t;
    int v = (i < N_NODES) ? g_cnt[i] : 0;
    s[t] = v;
    for (int off = 1; off < SCAN_BLOCK; off <<= 1) {
        __syncthreads();
        int u = (t >= off) ? s[t - off] : 0;
        __syncthreads();
        s[t] += u;
    }
    __syncthreads();
    if (i < N_NODES) g_incl[i] = s[t];
    if (t == SCAN_BLOCK - 1) g_blocksum[blockIdx.x] = s[t];
}

__global__ void scanB_kernel() {
    __shared__ int s[512];
    int t = threadIdx.x;
    int v = (t < SCAN_NBLK) ? g_blocksum[t] : 0;
    s[t] = v;
    for (int off = 1; off < 512; off <<= 1) {
        __syncthreads();
        int u = (t >= off) ? s[t - off] : 0;
        __syncthreads();
        s[t] += u;
    }
    __syncthreads();
    if (t < SCAN_NBLK) g_blocksum[t] = s[t] - v;   // exclusive
}

__global__ void scanC_kernel() {
    int i = blockIdx.x * blockDim.x + threadIdx.x;
    if (i < N_NODES) {
        int excl = g_blocksum[i / SCAN_BLOCK] + g_incl[i] - g_cnt[i];
        g_rowptr[i] = excl;
        g_cursor[i] = excl;
    }
    if (i == 0) g_rowptr[N_NODES] = N_EDGES;
}

__global__ void fill_kernel(const int* __restrict__ ei) {
    int e = blockIdx.x * blockDim.x + threadIdx.x;
    if (e < N_EDGES) {
        int src = __ldg(ei + e);
        int dst = __ldg(ei + N_EDGES + e);
        int pos = atomicAdd(&g_cursor[dst], 1);
        g_col[pos] = src;
    }
}

// ---------------------------------------------------------------------------
// gather: agg[n] = (1/max(deg,1)) * sum_{e in CSR row n} x[col[e]]
// ---------------------------------------------------------------------------
__device__ __forceinline__ const float4* xrow(const float* xu, const float* xi,
                                              int r, int lane) {
    const float* base = (r < NUM_USERS) ? (xu + (size_t)r * HIDDEN)
                                        : (xi + (size_t)(r - NUM_USERS) * HIDDEN);
    return (const float4*)(base + lane * 4);
}

__global__ __launch_bounds__(256) void gather_kernel(
    const float* __restrict__ xu, const float* __restrict__ xi) {
    int node = blockIdx.x * (blockDim.x >> 5) + (threadIdx.x >> 5);
    int lane = threadIdx.x & 31;
    if (node >= N_NODES) return;
    int beg = g_rowptr[node];
    int end = g_rowptr[node + 1];
    float invd = 1.0f / fmaxf((float)(end - beg), 1.0f);

    float4 acc = make_float4(0.f, 0.f, 0.f, 0.f);
    int e = beg;
    for (; e + 4 <= end; e += 4) {
        int s0 = __ldg(&g_col[e]);
        int s1 = __ldg(&g_col[e + 1]);
        int s2 = __ldg(&g_col[e + 2]);
        int s3 = __ldg(&g_col[e + 3]);
        float4 v0 = *xrow(xu, xi, s0, lane);
        float4 v1 = *xrow(xu, xi, s1, lane);
        float4 v2 = *xrow(xu, xi, s2, lane);
        float4 v3 = *xrow(xu, xi, s3, lane);
        acc.x += v0.x + v1.x + v2.x + v3.x;
        acc.y += v0.y + v1.y + v2.y + v3.y;
        acc.z += v0.z + v1.z + v2.z + v3.z;
        acc.w += v0.w + v1.w + v2.w + v3.w;
    }
    for (; e < end; e++) {
        int s0 = __ldg(&g_col[e]);
        float4 v0 = *xrow(xu, xi, s0, lane);
        acc.x += v0.x; acc.y += v0.y; acc.z += v0.z; acc.w += v0.w;
    }
    acc.x *= invd; acc.y *= invd; acc.z *= invd; acc.w *= invd;
    *(float4*)(g_agg + (size_t)node * HIDDEN + lane * 4) = acc;
}

// ---------------------------------------------------------------------------
// tf32 helpers
// ---------------------------------------------------------------------------
__device__ __forceinline__ uint32_t f2tf(float a) {
    uint32_t r;
    asm("cvt.rna.tf32.f32 %0, %1;" : "=r"(r) : "f"(a));
    return r;
}

__device__ __forceinline__ void mma_tf32(float* d,
                                         uint32_t a0, uint32_t a1,
                                         uint32_t a2, uint32_t a3,
                                         uint32_t b0, uint32_t b1) {
    asm("mma.sync.aligned.m16n8k8.row.col.f32.tf32.tf32.f32 "
        "{%0,%1,%2,%3}, {%4,%5,%6,%7}, {%8,%9}, {%0,%1,%2,%3};"
        : "+f"(d[0]), "+f"(d[1]), "+f"(d[2]), "+f"(d[3])
        : "r"(a0), "r"(a1), "r"(a2), "r"(a3), "r"(b0), "r"(b1));
}

// ---------------------------------------------------------------------------
// fused GEMM (3xTF32 tensor core):
//   out = relu( agg @ Wl^T + b + x @ Wr^T ),  M=100000, N=128, K=256
// block: 256 threads (8 warps), tile 64x128; warp tile 32x32 (grid 2m x 4n)
// K staged in chunks of 32; smem holds A/W tiles PRE-PERMUTED into
// mma fragment order (1 LDS.128 per A-frag, 1 LDS.64 per B-frag).
// ---------------------------------------------------------------------------
__global__ __launch_bounds__(256) void gemm_mma_kernel(
    const float* __restrict__ xu,
    const float* __restrict__ xi,
    const float* __restrict__ Wl,
    const float* __restrict__ Wr,
    const float* __restrict__ bias,
    float* __restrict__ out) {
    // As[((s*4+mt)*32+lane)*4 + (h*2+rh)] : 4 s-steps, 4 m16 tiles
    // Bs[((s*16+nt)*32+lane)*2 + h]       : 4 s-steps, 16 n8 tiles
    __shared__ float As[2048];
    __shared__ float Bs[4096];

    const int tid  = threadIdx.x;
    const int warp = tid >> 5;
    const int lane = tid & 31;
    const int wm   = warp & 1;      // m 32-tile
    const int wn   = warp >> 1;     // n 32-tile
    const int m0   = blockIdx.x * 64;

    float acc[2][4][4];
#pragma unroll
    for (int i = 0; i < 2; i++)
#pragma unroll
        for (int j = 0; j < 4; j++)
#pragma unroll
            for (int r = 0; r < 4; r++) acc[i][j][r] = 0.f;

    for (int kc = 0; kc < 8; ++kc) {
        const int kk = kc << 5;                 // global k base (0..224)
        const bool firstHalf = (kk < HIDDEN);
        const int ko = firstHalf ? kk : kk - HIDDEN;
        const float* Wsrc = firstHalf ? Wl : Wr;

        __syncthreads();   // previous iteration's reads done before overwrite

        // ---- load A tile (64 rows x 32 k), permute into fragment order ----
#pragma unroll
        for (int r = 0; r < 2; r++) {
            int idx = tid + (r << 8);           // 0..511
            int row = idx >> 3;                 // 0..63
            int cq  = idx & 7;                  // float4 group: k = cq*4..cq*4+3
            int grow = m0 + row;
            float4 v = make_float4(0.f, 0.f, 0.f, 0.f);
            if (grow < N_NODES) {
                const float* src;
                if (firstHalf) src = g_agg + (size_t)grow * HIDDEN;
                else src = (grow < NUM_USERS)
                               ? xu + (size_t)grow * HIDDEN
                               : xi + (size_t)(grow - NUM_USERS) * HIDDEN;
                v = *(const float4*)(src + ko + (cq << 2));
            }
            int mt = row >> 4, rr = row & 15, gg = rr & 7, rh = rr >> 3;
#pragma unroll
            for (int e = 0; e < 4; e++) {
                int kl = (cq << 2) + e;
                int s = kl >> 3, c8 = kl & 7, tt = c8 & 3, h = c8 >> 2;
                int ln = (gg << 2) + tt;
                As[(((((s << 2) + mt) << 5) + ln) << 2) + (h << 1) + rh] =
                    ((const float*)&v)[e];
            }
        }

        // ---- load B tile (128 n x 32 k), permute into fragment order ----
#pragma unroll
        for (int r = 0; r < 4; r++) {
            int idx = tid + (r << 8);           // 0..1023
            int n  = idx >> 3;                  // 0..127
            int cq = idx & 7;
            float4 v = *(const float4*)(Wsrc + n * HIDDEN + ko + (cq << 2));
            int nt = n >> 3, gg = n & 7;
#pragma unroll
            for (int e = 0; e < 4; e++) {
                int kl = (cq << 2) + e;
                int s = kl >> 3, c8 = kl & 7, tt = c8 & 3, h = c8 >> 2;
                int ln = (gg << 2) + tt;
                Bs[(((((s << 4) + nt) << 5) + ln) << 1) + h] =
                    ((const float*)&v)[e];
            }
        }
        __syncthreads();

        // ---- 4 k8 steps ----
#pragma unroll
        for (int s = 0; s < 4; s++) {
            uint32_t ahi[2][4], alo[2][4];
#pragma unroll
            for (int i = 0; i < 2; i++) {
                int mt = (wm << 1) + i;
                const float4 a = *(const float4*)
                    &As[((((s << 2) + mt) << 5) + lane) << 2];
                const float af[4] = {a.x, a.y, a.z, a.w};
#pragma unroll
                for (int r = 0; r < 4; r++) {
                    uint32_t hi = f2tf(af[r]);
                    ahi[i][r] = hi;
                    alo[i][r] = f2tf(af[r] - __uint_as_float(hi));
                }
            }
            uint32_t bhi[4][2], blo[4][2];
#pragma unroll
            for (int j = 0; j < 4; j++) {
                int nt = (wn << 2) + j;
                const float2 b = *(const float2*)
                    &Bs[((((s << 4) + nt) << 5) + lane) << 1];
                const float bf[2] = {b.x, b.y};
#pragma unroll
                for (int r = 0; r < 2; r++) {
                    uint32_t hi = f2tf(bf[r]);
                    bhi[j][r] = hi;
                    blo[j][r] = f2tf(bf[r] - __uint_as_float(hi));
                }
            }
#pragma unroll
            for (int i = 0; i < 2; i++)
#pragma unroll
                for (int j = 0; j < 4; j++) {
                    mma_tf32(acc[i][j], ahi[i][0], ahi[i][1], ahi[i][2], ahi[i][3],
                             blo[j][0], blo[j][1]);
                    mma_tf32(acc[i][j], alo[i][0], alo[i][1], alo[i][2], alo[i][3],
                             bhi[j][0], bhi[j][1]);
                    mma_tf32(acc[i][j], ahi[i][0], ahi[i][1], ahi[i][2], ahi[i][3],
                             bhi[j][0], bhi[j][1]);
                }
        }
    }

    // ---- epilogue: bias + relu, float2 stores ----
    const int g = lane >> 2, t = lane & 3;
#pragma unroll
    for (int i = 0; i < 2; i++) {
        int rbase = m0 + (wm << 5) + (i << 4) + g;
#pragma unroll
        for (int j = 0; j < 4; j++) {
            int col = (wn << 5) + (j << 3) + (t << 1);
            float b0 = __ldg(bias + col);
            float b1 = __ldg(bias + col + 1);
            if (rbase < N_NODES) {
                float2 o;
                o.x = fmaxf(acc[i][j][0] + b0, 0.f);
                o.y = fmaxf(acc[i][j][1] + b1, 0.f);
                *(float2*)(out + (size_t)rbase * HIDDEN + col) = o;
            }
            if (rbase + 8 < N_NODES) {
                float2 o;
                o.x = fmaxf(acc[i][j][2] + b0, 0.f);
                o.y = fmaxf(acc[i][j][3] + b1, 0.f);
                *(float2*)(out + (size_t)(rbase + 8) * HIDDEN + col) = o;
            }
        }
    }
}

// ---------------------------------------------------------------------------
// launch
// ---------------------------------------------------------------------------
extern "C" void kernel_launch(void* const* d_in, const int* in_sizes, int n_in,
                              void* d_out, int out_size) {
    const float* ue = (const float*)d_in[0];
    const float* ie = (const float*)d_in[1];
    const float* Wl = (const float*)d_in[2];
    const float* bl = (const float*)d_in[3];
    const float* Wr = (const float*)d_in[4];
    const int*   ei = (const int*)d_in[5];
    float* out = (float*)d_out;

    float* px1;
    cudaGetSymbolAddress((void**)&px1, g_x1);

    const int T = 256;
    const int node_blocks = (N_NODES + T - 1) / T;
    const int edge_blocks = (N_EDGES + T - 1) / T;
    const int gath_blocks = (N_NODES + 7) / 8;
    const int gemm_blocks = (N_NODES + 63) / 64;

    // CSR build (once; reused by both layers)
    zero_cnt_kernel<<<node_blocks, T>>>();
    hist_kernel<<<edge_blocks, T>>>(ei);
    scanA_kernel<<<SCAN_NBLK, SCAN_BLOCK>>>();
    scanB_kernel<<<1, 512>>>();
    scanC_kernel<<<node_blocks, T>>>();
    fill_kernel<<<edge_blocks, T>>>(ei);

    // layer 0
    gather_kernel<<<gath_blocks, T>>>(ue, ie);
    gemm_mma_kernel<<<gemm_blocks, 256>>>(ue, ie, Wl, Wr, bl, px1);

    // layer 1
    gather_kernel<<<gath_blocks, T>>>(px1, px1 + (size_t)NUM_USERS * HIDDEN);
    gemm_mma_kernel<<<gemm_blocks, 256>>>(px1, px1 + (size_t)NUM_USERS * HIDDEN,
                                          Wl + HIDDEN * HIDDEN,
                                          Wr + HIDDEN * HIDDEN,
                                          bl + HIDDEN, out);
}

// round 4
// speedup vs baseline: 4.0421x; 1.9587x over previous
#include <cuda_runtime.h>
#include <cuda_fp16.h>
#include <cstdint>

#define NUM_USERS 50000
#define NUM_ITEMS 50000
#define N_NODES   100000
#define HIDDEN    128
#define N_EDGES   1600000

#define SCAN_BLOCK 256
#define SCAN_NBLK  ((N_NODES + SCAN_BLOCK - 1) / SCAN_BLOCK)   // 391

// ---------------------------------------------------------------------------
// Scratch (static device globals; no runtime allocation)
// ---------------------------------------------------------------------------
__device__ __half g_xh0[(size_t)N_NODES * HIDDEN];   // fp16 input features
__device__ __half g_xh1[(size_t)N_NODES * HIDDEN];   // fp16 layer-0 output
__device__ __half g_aggh[(size_t)N_NODES * HIDDEN];  // fp16 aggregated (/deg)
__device__ __half g_wh[4 * HIDDEN * HIDDEN];         // Wl0,Wl1,Wr0,Wr1 fp16
__device__ int    g_cnt[N_NODES];
__device__ int    g_incl[N_NODES];
__device__ int    g_rowptr[N_NODES + 1];
__device__ int    g_cursor[N_NODES];
__device__ int    g_col[N_EDGES];
__device__ int    g_blocksum[SCAN_NBLK];

// ---------------------------------------------------------------------------
// CSR build: zero -> histogram -> 3-phase scan -> fill
// ---------------------------------------------------------------------------
__global__ void zero_cnt_kernel() {
    int i = blockIdx.x * blockDim.x + threadIdx.x;
    if (i < N_NODES) g_cnt[i] = 0;
}

__global__ void hist_kernel(const int* __restrict__ ei) {
    int e = blockIdx.x * blockDim.x + threadIdx.x;
    if (e < N_EDGES) atomicAdd(&g_cnt[__ldg(ei + N_EDGES + e)], 1);
}

__global__ void scanA_kernel() {
    __shared__ int s[SCAN_BLOCK];
    int t = threadIdx.x;
    int i = blockIdx.x * SCAN_BLOCK + t;
    int v = (i < N_NODES) ? g_cnt[i] : 0;
    s[t] = v;
    for (int off = 1; off < SCAN_BLOCK; off <<= 1) {
        __syncthreads();
        int u = (t >= off) ? s[t - off] : 0;
        __syncthreads();
        s[t] += u;
    }
    __syncthreads();
    if (i < N_NODES) g_incl[i] = s[t];
    if (t == SCAN_BLOCK - 1) g_blocksum[blockIdx.x] = s[t];
}

__global__ void scanB_kernel() {
    __shared__ int s[512];
    int t = threadIdx.x;
    int v = (t < SCAN_NBLK) ? g_blocksum[t] : 0;
    s[t] = v;
    for (int off = 1; off < 512; off <<= 1) {
        __syncthreads();
        int u = (t >= off) ? s[t - off] : 0;
        __syncthreads();
        s[t] += u;
    }
    __syncthreads();
    if (t < SCAN_NBLK) g_blocksum[t] = s[t] - v;   // exclusive
}

__global__ void scanC_kernel() {
    int i = blockIdx.x * blockDim.x + threadIdx.x;
    if (i < N_NODES) {
        int excl = g_blocksum[i / SCAN_BLOCK] + g_incl[i] - g_cnt[i];
        g_rowptr[i] = excl;
        g_cursor[i] = excl;
    }
    if (i == 0) g_rowptr[N_NODES] = N_EDGES;
}

__global__ void fill_kernel(const int* __restrict__ ei) {
    int e = blockIdx.x * blockDim.x + threadIdx.x;
    if (e < N_EDGES) {
        int src = __ldg(ei + e);
        int dst = __ldg(ei + N_EDGES + e);
        int pos = atomicAdd(&g_cursor[dst], 1);
        g_col[pos] = src;
    }
}

// ---------------------------------------------------------------------------
// fp16 conversions
// ---------------------------------------------------------------------------
__device__ __forceinline__ uint2 f4_to_h4(float4 v) {
    __half2 a = __float22half2_rn(make_float2(v.x, v.y));
    __half2 b = __float22half2_rn(make_float2(v.z, v.w));
    uint2 r;
    r.x = *(uint32_t*)&a;
    r.y = *(uint32_t*)&b;
    return r;
}

__global__ void convert_x0_kernel(const float* __restrict__ ue,
                                  const float* __restrict__ ie) {
    int i = blockIdx.x * blockDim.x + threadIdx.x;
    const int half4 = NUM_USERS * HIDDEN / 4;   // 1.6M float4 groups
    if (i < half4) {
        ((uint2*)g_xh0)[i] = f4_to_h4(((const float4*)ue)[i]);
    } else if (i < 2 * half4) {
        ((uint2*)g_xh0)[i] = f4_to_h4(((const float4*)ie)[i - half4]);
    }
}

// g_wh layout: [0]=Wl layer0, [1]=Wl layer1, [2]=Wr layer0, [3]=Wr layer1
__global__ void convert_w_kernel(const float* __restrict__ Wl,
                                 const float* __restrict__ Wr) {
    int i = blockIdx.x * blockDim.x + threadIdx.x;
    const int wq = 2 * HIDDEN * HIDDEN / 4;   // 8192 float4 per (Wl|Wr)
    if (i < wq) {
        ((uint2*)g_wh)[i] = f4_to_h4(((const float4*)Wl)[i]);
    } else if (i < 2 * wq) {
        ((uint2*)g_wh)[i + 0] = f4_to_h4(((const float4*)Wr)[i - wq]);
    }
}

// ---------------------------------------------------------------------------
// gather: aggh[n] = fp16( (1/max(deg,1)) * sum x[col[e]] ), fp32 accumulate
// one warp per node; lane covers 4 fp16 (8 B) of the 256 B row
// ---------------------------------------------------------------------------
__device__ __forceinline__ void acc_row(float2& a0, float2& a1, uint2 v) {
    float2 f0 = __half22float2(*(__half2*)&v.x);
    float2 f1 = __half22float2(*(__half2*)&v.y);
    a0.x += f0.x; a0.y += f0.y;
    a1.x += f1.x; a1.y += f1.y;
}

__global__ __launch_bounds__(256) void gather_kernel(
    const __half* __restrict__ xh) {
    int node = blockIdx.x * (blockDim.x >> 5) + (threadIdx.x >> 5);
    int lane = threadIdx.x & 31;
    if (node >= N_NODES) return;
    int beg = g_rowptr[node];
    int end = g_rowptr[node + 1];
    float invd = 1.0f / fmaxf((float)(end - beg), 1.0f);

    float2 a0 = make_float2(0.f, 0.f), a1 = make_float2(0.f, 0.f);
    int e = beg;
    for (; e + 4 <= end; e += 4) {
        int s0 = __ldg(&g_col[e]);
        int s1 = __ldg(&g_col[e + 1]);
        int s2 = __ldg(&g_col[e + 2]);
        int s3 = __ldg(&g_col[e + 3]);
        uint2 v0 = *(const uint2*)(xh + (size_t)s0 * HIDDEN + lane * 4);
        uint2 v1 = *(const uint2*)(xh + (size_t)s1 * HIDDEN + lane * 4);
        uint2 v2 = *(const uint2*)(xh + (size_t)s2 * HIDDEN + lane * 4);
        uint2 v3 = *(const uint2*)(xh + (size_t)s3 * HIDDEN + lane * 4);
        acc_row(a0, a1, v0);
        acc_row(a0, a1, v1);
        acc_row(a0, a1, v2);
        acc_row(a0, a1, v3);
    }
    for (; e < end; e++) {
        int s0 = __ldg(&g_col[e]);
        uint2 v0 = *(const uint2*)(xh + (size_t)s0 * HIDDEN + lane * 4);
        acc_row(a0, a1, v0);
    }
    a0.x *= invd; a0.y *= invd; a1.x *= invd; a1.y *= invd;
    __half2 h0 = __float22half2_rn(a0);
    __half2 h1 = __float22half2_rn(a1);
    uint2 st;
    st.x = *(uint32_t*)&h0;
    st.y = *(uint32_t*)&h1;
    *(uint2*)(g_aggh + (size_t)node * HIDDEN + lane * 4) = st;
}

// ---------------------------------------------------------------------------
// fp16 HMMA helpers
// ---------------------------------------------------------------------------
__device__ __forceinline__ void mma_f16(float* d,
                                        uint32_t a0, uint32_t a1,
                                        uint32_t a2, uint32_t a3,
                                        uint32_t b0, uint32_t b1) {
    asm("mma.sync.aligned.m16n8k16.row.col.f32.f16.f16.f32 "
        "{%0,%1,%2,%3}, {%4,%5,%6,%7}, {%8,%9}, {%0,%1,%2,%3};"
        : "+f"(d[0]), "+f"(d[1]), "+f"(d[2]), "+f"(d[3])
        : "r"(a0), "r"(a1), "r"(a2), "r"(a3), "r"(b0), "r"(b1));
}

// ---------------------------------------------------------------------------
// fused GEMM (fp16 tensor core, fp32 accum):
//   out = relu( aggh @ Wl^T + b + xh @ Wr^T ),  M=100000, N=128, K=256
// block 256 thr (8 warps), tile 64x128, warp 32x32; K in 4 chunks of 64.
// smem pre-permuted into m16n8k16 fragment order:
//   A frag = 1 LDS.128 (4 u32), B frag = 1 LDS.64 (2 u32)
// outh != nullptr -> write fp16 (layer 0); else write fp32 to outf (layer 1)
// ---------------------------------------------------------------------------
__global__ __launch_bounds__(256) void gemm_h_kernel(
    const __half* __restrict__ xh,
    const __half* __restrict__ whl,
    const __half* __restrict__ whr,
    const float* __restrict__ bias,
    float* __restrict__ outf,
    __half* __restrict__ outh) {
    __shared__ uint32_t AsU[2048];   // 4 s * 4 mt * 32 lane * 4 reg
    __shared__ uint32_t BsU[4096];   // 4 s * 16 nt * 32 lane * 2 reg

    const int tid  = threadIdx.x;
    const int warp = tid >> 5;
    const int lane = tid & 31;
    const int wm   = warp & 1;
    const int wn   = warp >> 1;
    const int m0   = blockIdx.x * 64;

    float acc[2][4][4];
#pragma unroll
    for (int i = 0; i < 2; i++)
#pragma unroll
        for (int j = 0; j < 4; j++)
#pragma unroll
            for (int r = 0; r < 4; r++) acc[i][j][r] = 0.f;

    for (int kc = 0; kc < 4; ++kc) {
        const int ko = (kc & 1) << 6;                  // 0 or 64
        const __half* Asrc = (kc < 2) ? g_aggh : xh;
        const __half* Wsrc = (kc < 2) ? whl : whr;

        __syncthreads();

        // ---- A tile: 64 rows x 64 k fp16, permuted ----
#pragma unroll
        for (int r = 0; r < 2; r++) {
            int idx = tid + (r << 8);          // 0..511
            int row = idx >> 3;                // 0..63
            int q   = idx & 7;                 // uint4 (8 fp16) index
            int grow = m0 + row;
            uint4 v = make_uint4(0, 0, 0, 0);
            if (grow < N_NODES)
                v = *(const uint4*)(Asrc + (size_t)grow * HIDDEN + ko + (q << 3));
            int s  = q >> 1;
            int h  = q & 1;
            int mt = row >> 4;
            int rh = (row >> 3) & 1;
            int reg = (h << 1) | rh;
            int base = ((((s << 2) | mt) << 5) | ((row & 7) << 2)) << 2;
            AsU[base + 0 * 4 + reg] = v.x;
            AsU[base + 1 * 4 + reg] = v.y;
            AsU[base + 2 * 4 + reg] = v.z;
            AsU[base + 3 * 4 + reg] = v.w;
        }

        // ---- B tile: 128 n x 64 k fp16, permuted ----
#pragma unroll
        for (int r = 0; r < 4; r++) {
            int idx = tid + (r << 8);          // 0..1023
            int n  = idx >> 3;                 // 0..127
            int q  = idx & 7;
            uint4 v = *(const uint4*)(Wsrc + n * HIDDEN + ko + (q << 3));
            int s  = q >> 1;
            int reg = q & 1;
            int nt = n >> 3;
            int base = (((s << 4) | nt) << 5 | ((n & 7) << 2)) << 1;
            BsU[base + 0 * 2 + reg] = v.x;
            BsU[base + 1 * 2 + reg] = v.y;
            BsU[base + 2 * 2 + reg] = v.z;
            BsU[base + 3 * 2 + reg] = v.w;
        }
        __syncthreads();

        // ---- 4 k16 steps ----
#pragma unroll
        for (int s = 0; s < 4; s++) {
            uint4 af[2];
#pragma unroll
            for (int i = 0; i < 2; i++) {
                int mt = (wm << 1) + i;
                af[i] = *(const uint4*)
                    &AsU[((((s << 2) | mt) << 5) | lane) << 2];
            }
            uint2 bf[4];
#pragma unroll
            for (int j = 0; j < 4; j++) {
                int nt = (wn << 2) + j;
                bf[j] = *(const uint2*)
                    &BsU[(((s << 4) | nt) << 5 | lane) << 1];
            }
#pragma unroll
            for (int i = 0; i < 2; i++)
#pragma unroll
                for (int j = 0; j < 4; j++)
                    mma_f16(acc[i][j], af[i].x, af[i].y, af[i].z, af[i].w,
                            bf[j].x, bf[j].y);
        }
    }

    // ---- epilogue: bias + relu ----
    const int g = lane >> 2, t = lane & 3;
#pragma unroll
    for (int i = 0; i < 2; i++) {
        int rbase = m0 + (wm << 5) + (i << 4) + g;
#pragma unroll
        for (int j = 0; j < 4; j++) {
            int col = (wn << 5) + (j << 3) + (t << 1);
            float b0 = __ldg(bias + col);
            float b1 = __ldg(bias + col + 1);
            float v00 = fmaxf(acc[i][j][0] + b0, 0.f);
            float v01 = fmaxf(acc[i][j][1] + b1, 0.f);
            float v10 = fmaxf(acc[i][j][2] + b0, 0.f);
            float v11 = fmaxf(acc[i][j][3] + b1, 0.f);
            if (outh) {
                if (rbase < N_NODES) {
                    __half2 h = __float22half2_rn(make_float2(v00, v01));
                    *(uint32_t*)(outh + (size_t)rbase * HIDDEN + col) =
                        *(uint32_t*)&h;
                }
                if (rbase + 8 < N_NODES) {
                    __half2 h = __float22half2_rn(make_float2(v10, v11));
                    *(uint32_t*)(outh + (size_t)(rbase + 8) * HIDDEN + col) =
                        *(uint32_t*)&h;
                }
            } else {
                if (rbase < N_NODES)
                    *(float2*)(outf + (size_t)rbase * HIDDEN + col) =
                        make_float2(v00, v01);
                if (rbase + 8 < N_NODES)
                    *(float2*)(outf + (size_t)(rbase + 8) * HIDDEN + col) =
                        make_float2(v10, v11);
            }
        }
    }
}

// ---------------------------------------------------------------------------
// launch
// ---------------------------------------------------------------------------
extern "C" void kernel_launch(void* const* d_in, const int* in_sizes, int n_in,
                              void* d_out, int out_size) {
    const float* ue = (const float*)d_in[0];
    const float* ie = (const float*)d_in[1];
    const float* Wl = (const float*)d_in[2];
    const float* bl = (const float*)d_in[3];
    const float* Wr = (const float*)d_in[4];
    const int*   ei = (const int*)d_in[5];
    float* out = (float*)d_out;

    __half *pxh0, *pxh1, *pwh;
    cudaGetSymbolAddress((void**)&pxh0, g_xh0);
    cudaGetSymbolAddress((void**)&pxh1, g_xh1);
    cudaGetSymbolAddress((void**)&pwh, g_wh);

    const int T = 256;
    const int node_blocks = (N_NODES + T - 1) / T;
    const int edge_blocks = (N_EDGES + T - 1) / T;
    const int gath_blocks = (N_NODES + 7) / 8;
    const int gemm_blocks = (N_NODES + 63) / 64;
    const int cvx_blocks  = (2 * NUM_USERS * HIDDEN / 4 + T - 1) / T;
    const int cvw_blocks  = (4 * HIDDEN * HIDDEN / 4 + T - 1) / T;

    // conversions + CSR build
    convert_x0_kernel<<<cvx_blocks, T>>>(ue, ie);
    convert_w_kernel<<<cvw_blocks, T>>>(Wl, Wr);
    zero_cnt_kernel<<<node_blocks, T>>>();
    hist_kernel<<<edge_blocks, T>>>(ei);
    scanA_kernel<<<SCAN_NBLK, SCAN_BLOCK>>>();
    scanB_kernel<<<1, 512>>>();
    scanC_kernel<<<node_blocks, T>>>();
    fill_kernel<<<edge_blocks, T>>>(ei);

    const int HH = HIDDEN * HIDDEN;
    // layer 0: whl = g_wh[0], whr = g_wh[2]
    gather_kernel<<<gath_blocks, T>>>(pxh0);
    gemm_h_kernel<<<gemm_blocks, 256>>>(pxh0, pwh, pwh + 2 * HH, bl,
                                        nullptr, pxh1);
    // layer 1: whl = g_wh[1], whr = g_wh[3]
    gather_kernel<<<gath_blocks, T>>>(pxh1);
    gemm_h_kernel<<<gemm_blocks, 256>>>(pxh1, pwh + HH, pwh + 3 * HH,
                                        bl + HIDDEN, out, nullptr);
}

// round 5
// speedup vs baseline: 4.1803x; 1.0342x over previous
#include <cuda_runtime.h>
#include <cuda_fp16.h>
#include <cstdint>

#define NUM_USERS 50000
#define NUM_ITEMS 50000
#define N_NODES   100000
#define HIDDEN    128
#define N_EDGES   1600000

#define SCAN_BLOCK 256
#define SCAN_NBLK  ((N_NODES + SCAN_BLOCK - 1) / SCAN_BLOCK)   // 391

// ---------------------------------------------------------------------------
// Scratch (static device globals; no runtime allocation)
// ---------------------------------------------------------------------------
__device__ __half g_xh0[(size_t)N_NODES * HIDDEN];
__device__ __half g_xh1[(size_t)N_NODES * HIDDEN];
__device__ __half g_aggh[(size_t)N_NODES * HIDDEN];
__device__ __half g_wh[4 * HIDDEN * HIDDEN];         // Wl0,Wl1,Wr0,Wr1
__device__ int    g_cnt[N_NODES];
__device__ int    g_incl[N_NODES];
__device__ int    g_rowptr[N_NODES + 1];
__device__ int    g_cursor[N_NODES];
__device__ int    g_col[N_EDGES];
__device__ int    g_blocksum[SCAN_NBLK];

// ---------------------------------------------------------------------------
// fused prologue: convert x0 -> fp16, convert W -> fp16, zero cnt
// ---------------------------------------------------------------------------
__device__ __forceinline__ uint2 f4_to_h4(float4 v) {
    __half2 a = __float22half2_rn(make_float2(v.x, v.y));
    __half2 b = __float22half2_rn(make_float2(v.z, v.w));
    uint2 r;
    r.x = *(uint32_t*)&a;
    r.y = *(uint32_t*)&b;
    return r;
}

#define CVX_BLOCKS 12500   // 3.2M uint2 groups / 256
#define CVW_BLOCKS 64      // 16384 groups / 256
#define ZC_BLOCKS  SCAN_NBLK

__global__ void prologue_kernel(const float* __restrict__ ue,
                                const float* __restrict__ ie,
                                const float* __restrict__ Wl,
                                const float* __restrict__ Wr) {
    int bid = blockIdx.x;
    if (bid < CVX_BLOCKS) {
        int i = bid * 256 + threadIdx.x;
        const int half4 = NUM_USERS * HIDDEN / 4;
        if (i < half4)
            ((uint2*)g_xh0)[i] = f4_to_h4(((const float4*)ue)[i]);
        else
            ((uint2*)g_xh0)[i] = f4_to_h4(((const float4*)ie)[i - half4]);
    } else if (bid < CVX_BLOCKS + CVW_BLOCKS) {
        int i = (bid - CVX_BLOCKS) * 256 + threadIdx.x;
        const int wq = 2 * HIDDEN * HIDDEN / 4;
        if (i < wq)
            ((uint2*)g_wh)[i] = f4_to_h4(((const float4*)Wl)[i]);
        else
            ((uint2*)g_wh)[i] = f4_to_h4(((const float4*)Wr)[i - wq]);
    } else {
        int i = (bid - CVX_BLOCKS - CVW_BLOCKS) * 256 + threadIdx.x;
        if (i < N_NODES) g_cnt[i] = 0;
    }
}

// ---------------------------------------------------------------------------
// CSR build
// ---------------------------------------------------------------------------
__global__ void hist_kernel(const int* __restrict__ ei) {
    int e = (blockIdx.x * blockDim.x + threadIdx.x) * 2;
    if (e + 1 < N_EDGES) {
        int2 d = *(const int2*)(ei + N_EDGES + e);
        atomicAdd(&g_cnt[d.x], 1);
        atomicAdd(&g_cnt[d.y], 1);
    } else if (e < N_EDGES) {
        atomicAdd(&g_cnt[__ldg(ei + N_EDGES + e)], 1);
    }
}

__global__ void scanA_kernel() {
    __shared__ int s[SCAN_BLOCK];
    int t = threadIdx.x;
    int i = blockIdx.x * SCAN_BLOCK + t;
    int v = (i < N_NODES) ? g_cnt[i] : 0;
    s[t] = v;
    for (int off = 1; off < SCAN_BLOCK; off <<= 1) {
        __syncthreads();
        int u = (t >= off) ? s[t - off] : 0;
        __syncthreads();
        s[t] += u;
    }
    __syncthreads();
    if (i < N_NODES) g_incl[i] = s[t];
    if (t == SCAN_BLOCK - 1) g_blocksum[blockIdx.x] = s[t];
}

// scanC: per-block offset computed in-kernel (folds old scanB)
__global__ void scanC_kernel() {
    __shared__ int sh[SCAN_BLOCK];
    int t = threadIdx.x;
    int bid = blockIdx.x;
    int partial = 0;
    for (int i = t; i < bid; i += SCAN_BLOCK) partial += g_blocksum[i];
    sh[t] = partial;
    __syncthreads();
    for (int off = SCAN_BLOCK / 2; off > 0; off >>= 1) {
        if (t < off) sh[t] += sh[t + off];
        __syncthreads();
    }
    int blockoff = sh[0];
    int i = bid * SCAN_BLOCK + t;
    if (i < N_NODES) {
        int excl = blockoff + g_incl[i] - g_cnt[i];
        g_rowptr[i] = excl;
        g_cursor[i] = excl;
    }
    if (i == 0) g_rowptr[N_NODES] = N_EDGES;
}

__global__ void fill_kernel(const int* __restrict__ ei) {
    int e = (blockIdx.x * blockDim.x + threadIdx.x) * 2;
    if (e + 1 < N_EDGES) {
        int2 s = *(const int2*)(ei + e);
        int2 d = *(const int2*)(ei + N_EDGES + e);
        int p0 = atomicAdd(&g_cursor[d.x], 1);
        g_col[p0] = s.x;
        int p1 = atomicAdd(&g_cursor[d.y], 1);
        g_col[p1] = s.y;
    } else if (e < N_EDGES) {
        int src = __ldg(ei + e);
        int dst = __ldg(ei + N_EDGES + e);
        int pos = atomicAdd(&g_cursor[dst], 1);
        g_col[pos] = src;
    }
}

// ---------------------------------------------------------------------------
// gather: aggh[n] = fp16( (1/max(deg,1)) * sum x[col[e]] ), fp32 accumulate
// one warp per node; 8 edges in flight
// ---------------------------------------------------------------------------
__device__ __forceinline__ void acc_row(float2& a0, float2& a1, uint2 v) {
    float2 f0 = __half22float2(*(__half2*)&v.x);
    float2 f1 = __half22float2(*(__half2*)&v.y);
    a0.x += f0.x; a0.y += f0.y;
    a1.x += f1.x; a1.y += f1.y;
}

__global__ __launch_bounds__(256) void gather_kernel(
    const __half* __restrict__ xh) {
    int node = blockIdx.x * (blockDim.x >> 5) + (threadIdx.x >> 5);
    int lane = threadIdx.x & 31;
    if (node >= N_NODES) return;
    int beg = g_rowptr[node];
    int end = g_rowptr[node + 1];
    float invd = 1.0f / fmaxf((float)(end - beg), 1.0f);

    float2 a0 = make_float2(0.f, 0.f), a1 = make_float2(0.f, 0.f);
    int e = beg;
    for (; e + 8 <= end; e += 8) {
        int sidx[8];
#pragma unroll
        for (int u = 0; u < 8; u++) sidx[u] = __ldg(&g_col[e + u]);
        uint2 v[8];
#pragma unroll
        for (int u = 0; u < 8; u++)
            v[u] = *(const uint2*)(xh + (size_t)sidx[u] * HIDDEN + lane * 4);
#pragma unroll
        for (int u = 0; u < 8; u++) acc_row(a0, a1, v[u]);
    }
    for (; e < end; e++) {
        int s0 = __ldg(&g_col[e]);
        uint2 v0 = *(const uint2*)(xh + (size_t)s0 * HIDDEN + lane * 4);
        acc_row(a0, a1, v0);
    }
    a0.x *= invd; a0.y *= invd; a1.x *= invd; a1.y *= invd;
    __half2 h0 = __float22half2_rn(a0);
    __half2 h1 = __float22half2_rn(a1);
    uint2 st;
    st.x = *(uint32_t*)&h0;
    st.y = *(uint32_t*)&h1;
    *(uint2*)(g_aggh + (size_t)node * HIDDEN + lane * 4) = st;
}

// ---------------------------------------------------------------------------
// fp16 HMMA
// ---------------------------------------------------------------------------
__device__ __forceinline__ void mma_f16(float* d,
                                        uint32_t a0, uint32_t a1,
                                        uint32_t a2, uint32_t a3,
                                        uint32_t b0, uint32_t b1) {
    asm("mma.sync.aligned.m16n8k16.row.col.f32.f16.f16.f32 "
        "{%0,%1,%2,%3}, {%4,%5,%6,%7}, {%8,%9}, {%0,%1,%2,%3};"
        : "+f"(d[0]), "+f"(d[1]), "+f"(d[2]), "+f"(d[3])
        : "r"(a0), "r"(a1), "r"(a2), "r"(a3), "r"(b0), "r"(b1));
}

// ---------------------------------------------------------------------------
// fused GEMM (fp16 TC, fp32 accum), register-prefetch + 2-stage smem:
//   out = relu( aggh @ Wl^T + b + xh @ Wr^T ),  M=100000, N=128, K=256
// block 256 thr (8 warps), tile 64x128, warp 32x32; K in 4 chunks of 64.
// ---------------------------------------------------------------------------
__global__ __launch_bounds__(256) void gemm_h_kernel(
    const __half* __restrict__ xh,
    const __half* __restrict__ whl,
    const __half* __restrict__ whr,
    const float* __restrict__ bias,
    float* __restrict__ outf,
    __half* __restrict__ outh) {
    __shared__ uint32_t AsU[2][2048];   // 8 KB per stage
    __shared__ uint32_t BsU[2][4096];   // 16 KB per stage

    const int tid  = threadIdx.x;
    const int warp = tid >> 5;
    const int lane = tid & 31;
    const int wm   = warp & 1;
    const int wn   = warp >> 1;
    const int m0   = blockIdx.x * 64;

    float acc[2][4][4];
#pragma unroll
    for (int i = 0; i < 2; i++)
#pragma unroll
        for (int j = 0; j < 4; j++)
#pragma unroll
            for (int r = 0; r < 4; r++) acc[i][j][r] = 0.f;

    uint4 ra[2], rb[4];

    // ---- load chunk kc into registers ----
    auto ldg_chunk = [&](int kc) {
        const int ko = (kc & 1) << 6;
        const __half* Asrc = (kc < 2) ? g_aggh : xh;
        const __half* Wsrc = (kc < 2) ? whl : whr;
#pragma unroll
        for (int r = 0; r < 2; r++) {
            int idx = tid + (r << 8);
            int row = idx >> 3;
            int q   = idx & 7;
            int grow = m0 + row;
            ra[r] = make_uint4(0, 0, 0, 0);
            if (grow < N_NODES)
                ra[r] = *(const uint4*)(Asrc + (size_t)grow * HIDDEN + ko + (q << 3));
        }
#pragma unroll
        for (int r = 0; r < 4; r++) {
            int idx = tid + (r << 8);
            int n  = idx >> 3;
            int q  = idx & 7;
            rb[r] = *(const uint4*)(Wsrc + n * HIDDEN + ko + (q << 3));
        }
    };

    // ---- permute registers into smem stage ----
    auto sts_chunk = [&](int stage) {
#pragma unroll
        for (int r = 0; r < 2; r++) {
            int idx = tid + (r << 8);
            int row = idx >> 3;
            int q   = idx & 7;
            int s  = q >> 1;
            int h  = q & 1;
            int mt = row >> 4;
            int rh = (row >> 3) & 1;
            int reg = (h << 1) | rh;
            int base = ((((s << 2) | mt) << 5) | ((row & 7) << 2)) << 2;
            AsU[stage][base + 0 * 4 + reg] = ra[r].x;
            AsU[stage][base + 1 * 4 + reg] = ra[r].y;
            AsU[stage][base + 2 * 4 + reg] = ra[r].z;
            AsU[stage][base + 3 * 4 + reg] = ra[r].w;
        }
#pragma unroll
        for (int r = 0; r < 4; r++) {
            int idx = tid + (r << 8);
            int n  = idx >> 3;
            int q  = idx & 7;
            int s  = q >> 1;
            int reg = q & 1;
            int nt = n >> 3;
            int base = (((s << 4) | nt) << 5 | ((n & 7) << 2)) << 1;
            BsU[stage][base + 0 * 2 + reg] = rb[r].x;
            BsU[stage][base + 1 * 2 + reg] = rb[r].y;
            BsU[stage][base + 2 * 2 + reg] = rb[r].z;
            BsU[stage][base + 3 * 2 + reg] = rb[r].w;
        }
    };

    // prologue: chunk 0 into stage 0
    ldg_chunk(0);
    sts_chunk(0);
    __syncthreads();

    for (int kc = 0; kc < 4; ++kc) {
        const int stage = kc & 1;
        if (kc < 3) ldg_chunk(kc + 1);   // latency hidden under compute

        // ---- 4 k16 steps from smem[stage] ----
#pragma unroll
        for (int s = 0; s < 4; s++) {
            uint4 af[2];
#pragma unroll
            for (int i = 0; i < 2; i++) {
                int mt = (wm << 1) + i;
                af[i] = *(const uint4*)
                    &AsU[stage][((((s << 2) | mt) << 5) | lane) << 2];
            }
            uint2 bf[4];
#pragma unroll
            for (int j = 0; j < 4; j++) {
                int nt = (wn << 2) + j;
                bf[j] = *(const uint2*)
                    &BsU[stage][(((s << 4) | nt) << 5 | lane) << 1];
            }
#pragma unroll
            for (int i = 0; i < 2; i++)
#pragma unroll
                for (int j = 0; j < 4; j++)
                    mma_f16(acc[i][j], af[i].x, af[i].y, af[i].z, af[i].w,
                            bf[j].x, bf[j].y);
        }

        if (kc < 3) {
            sts_chunk(stage ^ 1);
            __syncthreads();
        }
    }

    // ---- epilogue: bias + relu ----
    const int g = lane >> 2, t = lane & 3;
#pragma unroll
    for (int i = 0; i < 2; i++) {
        int rbase = m0 + (wm << 5) + (i << 4) + g;
#pragma unroll
        for (int j = 0; j < 4; j++) {
            int col = (wn << 5) + (j << 3) + (t << 1);
            float b0 = __ldg(bias + col);
            float b1 = __ldg(bias + col + 1);
            float v00 = fmaxf(acc[i][j][0] + b0, 0.f);
            float v01 = fmaxf(acc[i][j][1] + b1, 0.f);
            float v10 = fmaxf(acc[i][j][2] + b0, 0.f);
            float v11 = fmaxf(acc[i][j][3] + b1, 0.f);
            if (outh) {
                if (rbase < N_NODES) {
                    __half2 h = __float22half2_rn(make_float2(v00, v01));
                    *(uint32_t*)(outh + (size_t)rbase * HIDDEN + col) =
                        *(uint32_t*)&h;
                }
                if (rbase + 8 < N_NODES) {
                    __half2 h = __float22half2_rn(make_float2(v10, v11));
                    *(uint32_t*)(outh + (size_t)(rbase + 8) * HIDDEN + col) =
                        *(uint32_t*)&h;
                }
            } else {
                if (rbase < N_NODES)
                    *(float2*)(outf + (size_t)rbase * HIDDEN + col) =
                        make_float2(v00, v01);
                if (rbase + 8 < N_NODES)
                    *(float2*)(outf + (size_t)(rbase + 8) * HIDDEN + col) =
                        make_float2(v10, v11);
            }
        }
    }
}

// ---------------------------------------------------------------------------
// launch
// ---------------------------------------------------------------------------
extern "C" void kernel_launch(void* const* d_in, const int* in_sizes, int n_in,
                              void* d_out, int out_size) {
    const float* ue = (const float*)d_in[0];
    const float* ie = (const float*)d_in[1];
    const float* Wl = (const float*)d_in[2];
    const float* bl = (const float*)d_in[3];
    const float* Wr = (const float*)d_in[4];
    const int*   ei = (const int*)d_in[5];
    float* out = (float*)d_out;

    __half *pxh0, *pxh1, *pwh;
    cudaGetSymbolAddress((void**)&pxh0, g_xh0);
    cudaGetSymbolAddress((void**)&pxh1, g_xh1);
    cudaGetSymbolAddress((void**)&pwh, g_wh);

    const int T = 256;
    const int edge2_blocks = (N_EDGES / 2 + T - 1) / T;   // 3125
    const int gath_blocks  = (N_NODES + 7) / 8;
    const int gemm_blocks  = (N_NODES + 63) / 64;

    // prologue (convert x0/W + zero cnt) + CSR build
    prologue_kernel<<<CVX_BLOCKS + CVW_BLOCKS + ZC_BLOCKS, T>>>(ue, ie, Wl, Wr);
    hist_kernel<<<edge2_blocks, T>>>(ei);
    scanA_kernel<<<SCAN_NBLK, SCAN_BLOCK>>>();
    scanC_kernel<<<SCAN_NBLK, SCAN_BLOCK>>>();
    fill_kernel<<<edge2_blocks, T>>>(ei);

    const int HH = HIDDEN * HIDDEN;
    // layer 0
    gather_kernel<<<gath_blocks, T>>>(pxh0);
    gemm_h_kernel<<<gemm_blocks, 256>>>(pxh0, pwh, pwh + 2 * HH, bl,
                                        nullptr, pxh1);
    // layer 1
    gather_kernel<<<gath_blocks, T>>>(pxh1);
    gemm_h_kernel<<<gemm_blocks, 256>>>(pxh1, pwh + HH, pwh + 3 * HH,
                                        bl + HIDDEN, out, nullptr);
}